// round 1
// baseline (speedup 1.0000x reference)
#include <cuda_runtime.h>
#include <math.h>

// Problem constants
#define B_    4
#define T_    2048
#define DM_   2048
#define H_    16
#define HKV_  4
#define D_    128
#define M_    (B_*T_)      // 8192 tokens
#define NQ_   (H_*D_)      // 2048
#define NKV_  (HKV_*D_)    // 512

// Scratch (device globals: allocation-free per harness rules)
__device__ float g_q  [M_*NQ_];       // 64 MB
__device__ float g_k  [M_*NKV_];      // 16 MB
__device__ float g_v  [M_*NKV_];      // 16 MB
__device__ float g_att[M_*NQ_];       // 64 MB
__device__ float g_rope[T_*64*2];     // cos/sin table, 1 MB

// ---------------------------------------------------------------------------
// RoPE table: cos/sin of t * 10000^(-f/64), computed in double for accuracy
// ---------------------------------------------------------------------------
__global__ void rope_table_kernel(float* __restrict__ tab) {
    int idx = blockIdx.x * blockDim.x + threadIdx.x;
    if (idx >= T_ * 64) return;
    int t = idx >> 6, f = idx & 63;
    double invf = exp(-((double)f / 64.0) * log(10000.0));
    float ang = (float)t * (float)invf;
    tab[idx*2 + 0] = (float)cos((double)ang);
    tab[idx*2 + 1] = (float)sin((double)ang);
}

// ---------------------------------------------------------------------------
// SGEMM: C[M,N] = A[M,K] @ W[N,K]^T   (both K-major / row-major, "NT")
// Tile 128x128x16, 256 threads, 8x8 per-thread microtile, reg prefetch.
// FUSE: RMSNorm (per 128-wide head row) + rotary epilogue for q/k GEMMs.
// Requires M%128==0, N%128==0, K%16==0 (true for all 4 GEMMs here).
// ---------------------------------------------------------------------------
template<bool FUSE>
__global__ __launch_bounds__(256)
void sgemm_nt(const float* __restrict__ A, const float* __restrict__ W,
              float* __restrict__ C, int M, int N, int K,
              const float* __restrict__ rope)
{
    __shared__ float As[16][132];
    __shared__ float Bs[16][132];
    const int tid = threadIdx.x;
    const int tx  = tid & 15;
    const int ty  = tid >> 4;
    const int bx  = blockIdx.x, by = blockIdx.y;

    const float* Ab = A + (by * 128) * K;
    const float* Wb = W + (bx * 128) * K;
    const int lr = tid >> 2;          // 0..63
    const int lc = (tid & 3) << 2;    // 0,4,8,12

    float4 pa0, pa1, pb0, pb1;
    float acc[8][8];
    #pragma unroll
    for (int i = 0; i < 8; ++i)
        #pragma unroll
        for (int j = 0; j < 8; ++j) acc[i][j] = 0.f;

    // prefetch k-tile 0
    pa0 = *(const float4*)(Ab + lr       * K + lc);
    pa1 = *(const float4*)(Ab + (lr+64)  * K + lc);
    pb0 = *(const float4*)(Wb + lr       * K + lc);
    pb1 = *(const float4*)(Wb + (lr+64)  * K + lc);

    const int KT = K >> 4;
    for (int kt = 0; kt < KT; ++kt) {
        // store prefetched tile (transposed) to smem
        As[lc+0][lr]    = pa0.x; As[lc+1][lr]    = pa0.y; As[lc+2][lr]    = pa0.z; As[lc+3][lr]    = pa0.w;
        As[lc+0][lr+64] = pa1.x; As[lc+1][lr+64] = pa1.y; As[lc+2][lr+64] = pa1.z; As[lc+3][lr+64] = pa1.w;
        Bs[lc+0][lr]    = pb0.x; Bs[lc+1][lr]    = pb0.y; Bs[lc+2][lr]    = pb0.z; Bs[lc+3][lr]    = pb0.w;
        Bs[lc+0][lr+64] = pb1.x; Bs[lc+1][lr+64] = pb1.y; Bs[lc+2][lr+64] = pb1.z; Bs[lc+3][lr+64] = pb1.w;
        __syncthreads();

        if (kt + 1 < KT) {  // issue next gmem loads before compute (latency overlap)
            const float* An = Ab + (kt + 1) * 16;
            const float* Wn = Wb + (kt + 1) * 16;
            pa0 = *(const float4*)(An + lr      * K + lc);
            pa1 = *(const float4*)(An + (lr+64) * K + lc);
            pb0 = *(const float4*)(Wn + lr      * K + lc);
            pb1 = *(const float4*)(Wn + (lr+64) * K + lc);
        }

        #pragma unroll
        for (int k = 0; k < 16; ++k) {
            float a[8], b[8];
            *(float4*)(a)   = *(const float4*)&As[k][ty*8];
            *(float4*)(a+4) = *(const float4*)&As[k][ty*8+4];
            *(float4*)(b)   = *(const float4*)&Bs[k][tx*8];
            *(float4*)(b+4) = *(const float4*)&Bs[k][tx*8+4];
            #pragma unroll
            for (int i = 0; i < 8; ++i)
                #pragma unroll
                for (int j = 0; j < 8; ++j)
                    acc[i][j] = fmaf(a[i], b[j], acc[i][j]);
        }
        __syncthreads();
    }

    const int row0 = by*128 + ty*8;
    const int col0 = bx*128 + tx*8;

    if (!FUSE) {
        #pragma unroll
        for (int i = 0; i < 8; ++i) {
            float* cp = C + (row0 + i) * N + col0;
            *(float4*)cp     = make_float4(acc[i][0],acc[i][1],acc[i][2],acc[i][3]);
            *(float4*)(cp+4) = make_float4(acc[i][4],acc[i][5],acc[i][6],acc[i][7]);
        }
    } else {
        // Per-head RMSNorm + rotary. Column block bx covers exactly one head
        // (D_=128=BN). Row reductions are over the 16 tx lanes (intra-warp).
        const float sgn = (tx < 8) ? 1.0f : -1.0f;
        #pragma unroll
        for (int i = 0; i < 8; ++i) {
            float ss = 0.f;
            #pragma unroll
            for (int j = 0; j < 8; ++j) ss += acc[i][j] * acc[i][j];
            ss += __shfl_xor_sync(0xffffffffu, ss, 8);
            ss += __shfl_xor_sync(0xffffffffu, ss, 4);
            ss += __shfl_xor_sync(0xffffffffu, ss, 2);
            ss += __shfl_xor_sync(0xffffffffu, ss, 1);
            const float sc = rsqrtf(ss * (1.0f/128.0f) + 1.1920928955078125e-07f);

            float vv[8], oo[8];
            #pragma unroll
            for (int j = 0; j < 8; ++j) vv[j] = acc[i][j] * sc;

            const int t = (row0 + i) & (T_ - 1);
            const float* rp = rope + t * 128;
            #pragma unroll
            for (int j = 0; j < 8; ++j) {
                // pair col j with col j^64 (held by lane tx^8, same j)
                float partner = __shfl_xor_sync(0xffffffffu, vv[j], 8);
                int f = (tx*8 + j) & 63;
                oo[j] = vv[j] * rp[f*2] + sgn * partner * rp[f*2 + 1];
            }
            float* cp = C + (row0 + i) * N + col0;
            *(float4*)cp     = make_float4(oo[0],oo[1],oo[2],oo[3]);
            *(float4*)(cp+4) = make_float4(oo[4],oo[5],oo[6],oo[7]);
        }
    }
}

// ---------------------------------------------------------------------------
// Flash attention, fp32, causal, GQA (q head h -> kv head h/4).
// Block: 256 threads, BM=64 q rows, BN=64 kv per iter, D=128.
// Thread (tx,ty): S microtile 4x4 (rows ty*4.., cols tx*4..),
//                 O microtile 4x8  (rows ty*4.., d-cols tx*8..).
// Dynamic smem 112 KB -> 2 CTAs/SM.
// ---------------------------------------------------------------------------
__global__ __launch_bounds__(256)
void flash_kernel(const float* __restrict__ Q, const float* __restrict__ K,
                  const float* __restrict__ V, float* __restrict__ Out)
{
    extern __shared__ float sm[];
    float* Qt = sm;                 // [128][64]  (d-major, transposed)
    float* Kt = sm + 128*64;        // [128][64]
    float* Vs = sm + 2*128*64;      // [64][128]  (row-major)
    float* Ps = sm + 3*128*64;      // [64][64]

    const int qt  = (int)gridDim.x - 1 - (int)blockIdx.x;  // big tiles first
    const int h   = blockIdx.y;
    const int b   = blockIdx.z;
    const int kvh = h >> 2;
    const int tid = threadIdx.x;
    const int tx  = tid & 15, ty = tid >> 4;

    const float scale = 0.08838834764831843f;  // 1/sqrt(128), folded into Q

    {   // load + transpose Q tile, pre-scaled
        const int m  = tid >> 2;
        const int d4 = tid & 3;
        const float* qp = Q + (b*T_ + qt*64 + m) * NQ_ + h*128;
        #pragma unroll
        for (int it = 0; it < 8; ++it) {
            int d = (it*4 + d4) * 4;
            float4 f = *(const float4*)(qp + d);
            Qt[(d+0)*64 + m] = f.x * scale;
            Qt[(d+1)*64 + m] = f.y * scale;
            Qt[(d+2)*64 + m] = f.z * scale;
            Qt[(d+3)*64 + m] = f.w * scale;
        }
    }

    float mi[4], li[4], O[4][8];
    #pragma unroll
    for (int i = 0; i < 4; ++i) {
        mi[i] = -1e30f; li[i] = 0.f;
        #pragma unroll
        for (int c = 0; c < 8; ++c) O[i][c] = 0.f;
    }

    for (int jt = 0; jt <= qt; ++jt) {
        __syncthreads();  // prior readers of Kt/Vs done (also covers Qt fill on iter 0)
        {   // load K (transposed) and V (row-major) tiles
            const int m  = tid >> 2;
            const int d4 = tid & 3;
            const float* kp = K + (b*T_ + jt*64 + m) * NKV_ + kvh*128;
            #pragma unroll
            for (int it = 0; it < 8; ++it) {
                int d = (it*4 + d4) * 4;
                float4 f = *(const float4*)(kp + d);
                Kt[(d+0)*64 + m] = f.x;
                Kt[(d+1)*64 + m] = f.y;
                Kt[(d+2)*64 + m] = f.z;
                Kt[(d+3)*64 + m] = f.w;
            }
            #pragma unroll
            for (int it = 0; it < 8; ++it) {
                int fi = tid + 256*it;
                int r  = fi >> 5;
                int c4 = (fi & 31) << 2;
                *(float4*)&Vs[r*128 + c4] =
                    *(const float4*)(V + (b*T_ + jt*64 + r) * NKV_ + kvh*128 + c4);
            }
        }
        __syncthreads();

        // S = Q K^T (Q pre-scaled)
        float s[4][4];
        #pragma unroll
        for (int i = 0; i < 4; ++i)
            #pragma unroll
            for (int j = 0; j < 4; ++j) s[i][j] = 0.f;
        #pragma unroll 4
        for (int d = 0; d < 128; ++d) {
            float qa[4], kb[4];
            *(float4*)qa = *(const float4*)&Qt[d*64 + ty*4];
            *(float4*)kb = *(const float4*)&Kt[d*64 + tx*4];
            #pragma unroll
            for (int i = 0; i < 4; ++i)
                #pragma unroll
                for (int j = 0; j < 4; ++j)
                    s[i][j] = fmaf(qa[i], kb[j], s[i][j]);
        }

        if (jt == qt) {  // causal mask on diagonal tile
            #pragma unroll
            for (int i = 0; i < 4; ++i)
                #pragma unroll
                for (int j = 0; j < 4; ++j)
                    if (tx*4 + j > ty*4 + i) s[i][j] = -1e30f;
        }

        // online softmax (row reductions over tx lanes)
        #pragma unroll
        for (int i = 0; i < 4; ++i) {
            float rm = fmaxf(fmaxf(s[i][0], s[i][1]), fmaxf(s[i][2], s[i][3]));
            rm = fmaxf(rm, __shfl_xor_sync(0xffffffffu, rm, 8));
            rm = fmaxf(rm, __shfl_xor_sync(0xffffffffu, rm, 4));
            rm = fmaxf(rm, __shfl_xor_sync(0xffffffffu, rm, 2));
            rm = fmaxf(rm, __shfl_xor_sync(0xffffffffu, rm, 1));
            float mn   = fmaxf(mi[i], rm);
            float corr = __expf(mi[i] - mn);
            mi[i] = mn;
            float rs = 0.f;
            #pragma unroll
            for (int j = 0; j < 4; ++j) { s[i][j] = __expf(s[i][j] - mn); rs += s[i][j]; }
            rs += __shfl_xor_sync(0xffffffffu, rs, 8);
            rs += __shfl_xor_sync(0xffffffffu, rs, 4);
            rs += __shfl_xor_sync(0xffffffffu, rs, 2);
            rs += __shfl_xor_sync(0xffffffffu, rs, 1);
            li[i] = li[i]*corr + rs;
            *(float4*)&Ps[(ty*4 + i)*64 + tx*4] = make_float4(s[i][0], s[i][1], s[i][2], s[i][3]);
            #pragma unroll
            for (int c = 0; c < 8; ++c) O[i][c] *= corr;
        }
        __syncthreads();  // Ps fully written before cross-thread reads

        // O += P @ V
        #pragma unroll 2
        for (int n = 0; n < 64; ++n) {
            float p0 = Ps[(ty*4+0)*64 + n];
            float p1 = Ps[(ty*4+1)*64 + n];
            float p2 = Ps[(ty*4+2)*64 + n];
            float p3 = Ps[(ty*4+3)*64 + n];
            float vb[8];
            *(float4*)vb     = *(const float4*)&Vs[n*128 + tx*8];
            *(float4*)(vb+4) = *(const float4*)&Vs[n*128 + tx*8 + 4];
            #pragma unroll
            for (int c = 0; c < 8; ++c) {
                O[0][c] = fmaf(p0, vb[c], O[0][c]);
                O[1][c] = fmaf(p1, vb[c], O[1][c]);
                O[2][c] = fmaf(p2, vb[c], O[2][c]);
                O[3][c] = fmaf(p3, vb[c], O[3][c]);
            }
        }
    }

    #pragma unroll
    for (int i = 0; i < 4; ++i) {
        float inv = 1.0f / li[i];
        float* op = Out + (b*T_ + qt*64 + ty*4 + i) * NQ_ + h*128 + tx*8;
        *(float4*)op     = make_float4(O[i][0]*inv, O[i][1]*inv, O[i][2]*inv, O[i][3]*inv);
        *(float4*)(op+4) = make_float4(O[i][4]*inv, O[i][5]*inv, O[i][6]*inv, O[i][7]*inv);
    }
}

// ---------------------------------------------------------------------------
// Zero the tail of the output buffer (spatial_norm = zeros(1), plus padding)
// ---------------------------------------------------------------------------
__global__ void zero_tail_kernel(float* __restrict__ out, long start, long total) {
    long idx = start + blockIdx.x * (long)blockDim.x + threadIdx.x;
    if (idx < total) out[idx] = 0.f;
}

// ---------------------------------------------------------------------------
extern "C" void kernel_launch(void* const* d_in, const int* in_sizes, int n_in,
                              void* d_out, int out_size) {
    const float* x  = (const float*)d_in[0];
    const float* Wq = (const float*)d_in[1];
    const float* Wk = (const float*)d_in[2];
    const float* Wv = (const float*)d_in[3];
    const float* Wo = (const float*)d_in[4];
    // d_in[5] = temp (unused by reference), d_in[6] = curvature (unused)
    float* out = (float*)d_out;

    float *q, *k, *v, *att, *rope;
    cudaGetSymbolAddress((void**)&q,    g_q);
    cudaGetSymbolAddress((void**)&k,    g_k);
    cudaGetSymbolAddress((void**)&v,    g_v);
    cudaGetSymbolAddress((void**)&att,  g_att);
    cudaGetSymbolAddress((void**)&rope, g_rope);

    rope_table_kernel<<<(T_*64 + 255)/256, 256>>>(rope);

    dim3 blk(256);
    sgemm_nt<true ><<<dim3(NQ_ /128, M_/128), blk>>>(x,   Wq, q,   M_, NQ_,  DM_, rope);
    sgemm_nt<true ><<<dim3(NKV_/128, M_/128), blk>>>(x,   Wk, k,   M_, NKV_, DM_, rope);
    sgemm_nt<false><<<dim3(NKV_/128, M_/128), blk>>>(x,   Wv, v,   M_, NKV_, DM_, nullptr);

    const int smem = (128*64 + 128*64 + 64*128 + 64*64) * (int)sizeof(float);  // 114688
    cudaFuncSetAttribute(flash_kernel, cudaFuncAttributeMaxDynamicSharedMemorySize, smem);
    flash_kernel<<<dim3(T_/64, H_, B_), blk, smem>>>(q, k, v, att);

    sgemm_nt<false><<<dim3(NQ_/128, M_/128), blk>>>(att, Wo, out, M_, NQ_, DM_, nullptr);

    long main_elems = (long)M_ * NQ_;
    long tail = (long)out_size - main_elems;
    if (tail > 0) {
        int nb = (int)((tail + 255) / 256);
        zero_tail_kernel<<<nb, 256>>>(out, main_elems, (long)out_size);
    }
}

// round 3
// speedup vs baseline: 1.7711x; 1.7711x over previous
#include <cuda_runtime.h>
#include <math.h>
#include <stdint.h>

// Problem constants
#define B_    4
#define T_    2048
#define DM_   2048
#define H_    16
#define HKV_  4
#define D_    128
#define M_    (B_*T_)      // 8192 tokens
#define NQ_   (H_*D_)      // 2048
#define NKV_  (HKV_*D_)    // 512

// Scratch (device globals: allocation-free per harness rules)
__device__ float g_q  [M_*NQ_];       // 64 MB
__device__ float g_k  [M_*NKV_];      // 16 MB
__device__ float g_v  [M_*NKV_];      // 16 MB
__device__ float g_att[M_*NQ_];       // 64 MB
__device__ float g_xr [M_*DM_];       // 64 MB  (x rounded to tf32)
__device__ float g_wq [NQ_*DM_];      // 16 MB
__device__ float g_wk [NKV_*DM_];     // 4 MB
__device__ float g_wv [NKV_*DM_];     // 4 MB
__device__ float g_wo [DM_*NQ_];      // 16 MB
__device__ float g_rope[T_*64*2];     // cos/sin table, 1 MB

// ---------------------------------------------------------------------------
// Helpers
// ---------------------------------------------------------------------------
__device__ __forceinline__ uint32_t smem_u32(const void* p) {
    uint32_t a;
    asm("{ .reg .u64 t; cvta.to.shared.u64 t, %1; cvt.u32.u64 %0, t; }" : "=r"(a) : "l"(p));
    return a;
}
__device__ __forceinline__ float rna_tf32(float v) {
    uint32_t b;
    asm("cvt.rna.tf32.f32 %0, %1;" : "=r"(b) : "f"(v));
    return __uint_as_float(b);
}

#define CP_ASYNC16(dst, src) \
    asm volatile("cp.async.cg.shared.global [%0], [%1], 16;" :: "r"(dst), "l"(src) : "memory")
#define CP_COMMIT()  asm volatile("cp.async.commit_group;" ::: "memory")
#define CP_WAIT(n)   asm volatile("cp.async.wait_group %0;" :: "n"(n) : "memory")

// mma.sync m16n8k8 tf32 (family-portable: compiles for plain sm_103)
#define MMA_TF32(c, a, b) \
    asm volatile("mma.sync.aligned.m16n8k8.row.col.f32.tf32.tf32.f32 " \
        "{%0,%1,%2,%3}, {%4,%5,%6,%7}, {%8,%9}, {%0,%1,%2,%3};" \
        : "+f"((c)[0]), "+f"((c)[1]), "+f"((c)[2]), "+f"((c)[3]) \
        : "r"((a)[0]), "r"((a)[1]), "r"((a)[2]), "r"((a)[3]), \
          "r"((b)[0]), "r"((b)[1]))

// ---------------------------------------------------------------------------
// RNA-round fp32 buffer to tf32 bit pattern (kills HMMA truncation bias)
// ---------------------------------------------------------------------------
__global__ void round_tf32_kernel(const float* __restrict__ in, float* __restrict__ out, long n4) {
    long i = (blockIdx.x * (long)blockDim.x + threadIdx.x);
    if (i >= n4) return;
    float4 v = ((const float4*)in)[i];
    v.x = rna_tf32(v.x); v.y = rna_tf32(v.y); v.z = rna_tf32(v.z); v.w = rna_tf32(v.w);
    ((float4*)out)[i] = v;
}

// ---------------------------------------------------------------------------
// RoPE table: cos/sin of t * 10000^(-f/64), computed in double for accuracy
// ---------------------------------------------------------------------------
__global__ void rope_table_kernel(float* __restrict__ tab) {
    int idx = blockIdx.x * blockDim.x + threadIdx.x;
    if (idx >= T_ * 64) return;
    int t = idx >> 6, f = idx & 63;
    double invf = exp(-((double)f / 64.0) * log(10000.0));
    float ang = (float)t * (float)invf;
    tab[idx*2 + 0] = (float)cos((double)ang);
    tab[idx*2 + 1] = (float)sin((double)ang);
}

// ---------------------------------------------------------------------------
// HMMA tf32 GEMM: C[M,N] = A[M,K] @ W[N,K]^T  (NT, K-major, tf32-rounded in)
// CTA 128x128x32, 256 threads (8 warps, 2m x 4n grid, 64x32 warp tile).
// Double-buffered cp.async. Row pad = 8 floats (stride 40) so the permuted-k
// float2 fragment loads are bank-conflict-free.
// k-permutation: logical mma k index j (0..7) <-> smem col k0+2j for j<4,
// and j+4 <-> k0+2j+1 — SAME permutation for A cols and B rows, so the
// k-summation is merely reordered.
// FUSE: per-head (128-wide) RMSNorm + rotary through a smem C-stage.
// ---------------------------------------------------------------------------
#define STAGE_F 10240            // floats per stage (A 5120 + B 5120)
#define STAGE_B (STAGE_F*4)      // 40960 bytes

template<bool FUSE>
__global__ __launch_bounds__(256)
void tc_gemm(const float* __restrict__ A, const float* __restrict__ W,
             float* __restrict__ C, int M, int N, int K,
             const float* __restrict__ rope)
{
    extern __shared__ float smf[];
    const uint32_t sbase = smem_u32(smf);

    const int tid  = threadIdx.x;
    const int lane = tid & 31;
    const int wid  = tid >> 5;
    const int warp_m = wid >> 2;        // 0..1
    const int warp_n = wid & 3;         // 0..3
    const int bx = blockIdx.x, by = blockIdx.y;

    const float* Ab = A + (size_t)(by * 128) * K;
    const float* Wb = W + (size_t)(bx * 128) * K;

    float acc[4][4][4];
    #pragma unroll
    for (int mi = 0; mi < 4; ++mi)
        #pragma unroll
        for (int ni = 0; ni < 4; ++ni)
            #pragma unroll
            for (int e = 0; e < 4; ++e) acc[mi][ni][e] = 0.f;

    const int KT = K >> 5;   // chunks of 32

    // ---- stage loader (cp.async): 128 rows x 32 floats per matrix ----
    auto load_stage = [&](int s, int kt) {
        uint32_t aS = sbase + s * STAGE_B;
        uint32_t bS = aS + 20480;
        const float* ap = Ab + kt * 32;
        const float* wp = Wb + kt * 32;
        #pragma unroll
        for (int it = 0; it < 4; ++it) {
            int idx = it * 256 + tid;
            int row = idx >> 3, seg = idx & 7;
            uint32_t so = (uint32_t)row * 160 + (uint32_t)seg * 16;
            CP_ASYNC16(aS + so, ap + (size_t)row * K + seg * 4);
            CP_ASYNC16(bS + so, wp + (size_t)row * K + seg * 4);
        }
    };

    load_stage(0, 0);
    CP_COMMIT();

    for (int kt = 0; kt < KT; ++kt) {
        const int cur = kt & 1;
        if (kt + 1 < KT) {
            load_stage(cur ^ 1, kt + 1);
            CP_COMMIT();
            CP_WAIT(1);      // stage kt resident; kt+1 in flight
        } else {
            CP_WAIT(0);
        }
        __syncthreads();

        const float* As_ = smf + cur * STAGE_F + warp_m * (64 * 40);
        const float* Bs_ = smf + cur * STAGE_F + 5120 + warp_n * (32 * 40);

        #pragma unroll
        for (int ks = 0; ks < 4; ++ks) {
            const int col = ks * 8 + 2 * (lane & 3);
            uint32_t a[4][4], b[4][2];
            #pragma unroll
            for (int ni = 0; ni < 4; ++ni) {
                float2 t = *(const float2*)&Bs_[(ni * 8 + (lane >> 2)) * 40 + col];
                b[ni][0] = __float_as_uint(t.x);
                b[ni][1] = __float_as_uint(t.y);
            }
            #pragma unroll
            for (int mi = 0; mi < 4; ++mi) {
                const int r = mi * 16 + (lane >> 2);
                float2 t0 = *(const float2*)&As_[r * 40 + col];
                float2 t1 = *(const float2*)&As_[(r + 8) * 40 + col];
                a[mi][0] = __float_as_uint(t0.x);
                a[mi][2] = __float_as_uint(t0.y);
                a[mi][1] = __float_as_uint(t1.x);
                a[mi][3] = __float_as_uint(t1.y);
            }
            #pragma unroll
            for (int mi = 0; mi < 4; ++mi)
                #pragma unroll
                for (int ni = 0; ni < 4; ++ni)
                    MMA_TF32(acc[mi][ni], a[mi], b[ni]);
        }
        __syncthreads();
    }

    if (!FUSE) {
        #pragma unroll
        for (int mi = 0; mi < 4; ++mi) {
            const int r = by * 128 + warp_m * 64 + mi * 16 + (lane >> 2);
            #pragma unroll
            for (int ni = 0; ni < 4; ++ni) {
                const int c = bx * 128 + warp_n * 32 + ni * 8 + (lane & 3) * 2;
                *(float2*)&C[(size_t)r * N + c]       = make_float2(acc[mi][ni][0], acc[mi][ni][1]);
                *(float2*)&C[(size_t)(r + 8) * N + c] = make_float2(acc[mi][ni][2], acc[mi][ni][3]);
            }
        }
    } else {
        // Stage C tile in smem (pad 129 -> conflict-free row reads), then
        // 128 threads each own one full 128-wide head row: RMSNorm + rotary
        // are thread-local. Streaming passes keep register count low.
        float* Cs = smf;  // 128*129 floats = 66048 B <= 2*STAGE_B (stages dead)
        #pragma unroll
        for (int mi = 0; mi < 4; ++mi) {
            const int r = warp_m * 64 + mi * 16 + (lane >> 2);
            #pragma unroll
            for (int ni = 0; ni < 4; ++ni) {
                const int c = warp_n * 32 + ni * 8 + (lane & 3) * 2;
                Cs[r * 129 + c]           = acc[mi][ni][0];
                Cs[r * 129 + c + 1]       = acc[mi][ni][1];
                Cs[(r + 8) * 129 + c]     = acc[mi][ni][2];
                Cs[(r + 8) * 129 + c + 1] = acc[mi][ni][3];
            }
        }
        __syncthreads();
        if (tid < 128) {
            const int row = by * 128 + tid;
            const float* cr = Cs + tid * 129;
            float ss = 0.f;
            #pragma unroll 16
            for (int j = 0; j < 128; ++j) ss += cr[j] * cr[j];
            const float sc = rsqrtf(ss * (1.0f/128.0f) + 1.1920928955078125e-07f);
            const float* rp = rope + (row & (T_ - 1)) * 128;
            float* op = C + (size_t)row * N + bx * 128;
            #pragma unroll
            for (int f4 = 0; f4 < 64; f4 += 4) {
                float4 o1, o2;
                #pragma unroll
                for (int e = 0; e < 4; ++e) {
                    const int f = f4 + e;
                    const float v1 = cr[f] * sc;
                    const float v2 = cr[f + 64] * sc;
                    const float cz = rp[2*f], sz = rp[2*f + 1];
                    (&o1.x)[e] =  v1 * cz + v2 * sz;
                    (&o2.x)[e] = -v1 * sz + v2 * cz;
                }
                *(float4*)(op + f4)      = o1;
                *(float4*)(op + f4 + 64) = o2;
            }
        }
    }
}

// ---------------------------------------------------------------------------
// Flash attention, fp32, causal, GQA (q head h -> kv head h/4).
// Block: 256 threads, BM=64 q rows, BN=64 kv per iter, D=128.
// Output rounded to tf32 (feeds the tf32 O-projection GEMM bias-free).
// ---------------------------------------------------------------------------
__global__ __launch_bounds__(256)
void flash_kernel(const float* __restrict__ Q, const float* __restrict__ K,
                  const float* __restrict__ V, float* __restrict__ Out)
{
    extern __shared__ float sm[];
    float* Qt = sm;                 // [128][64]  (d-major, transposed)
    float* Kt = sm + 128*64;        // [128][64]
    float* Vs = sm + 2*128*64;      // [64][128]  (row-major)
    float* Ps = sm + 3*128*64;      // [64][64]

    const int qt  = (int)gridDim.x - 1 - (int)blockIdx.x;  // big tiles first
    const int h   = blockIdx.y;
    const int b   = blockIdx.z;
    const int kvh = h >> 2;
    const int tid = threadIdx.x;
    const int tx  = tid & 15, ty = tid >> 4;

    const float scale = 0.08838834764831843f;  // 1/sqrt(128), folded into Q

    {   // load + transpose Q tile, pre-scaled
        const int m  = tid >> 2;
        const int d4 = tid & 3;
        const float* qp = Q + (size_t)(b*T_ + qt*64 + m) * NQ_ + h*128;
        #pragma unroll
        for (int it = 0; it < 8; ++it) {
            int d = (it*4 + d4) * 4;
            float4 f = *(const float4*)(qp + d);
            Qt[(d+0)*64 + m] = f.x * scale;
            Qt[(d+1)*64 + m] = f.y * scale;
            Qt[(d+2)*64 + m] = f.z * scale;
            Qt[(d+3)*64 + m] = f.w * scale;
        }
    }

    float mi[4], li[4], O[4][8];
    #pragma unroll
    for (int i = 0; i < 4; ++i) {
        mi[i] = -1e30f; li[i] = 0.f;
        #pragma unroll
        for (int c = 0; c < 8; ++c) O[i][c] = 0.f;
    }

    for (int jt = 0; jt <= qt; ++jt) {
        __syncthreads();
        {   // load K (transposed) and V (row-major) tiles
            const int m  = tid >> 2;
            const int d4 = tid & 3;
            const float* kp = K + (size_t)(b*T_ + jt*64 + m) * NKV_ + kvh*128;
            #pragma unroll
            for (int it = 0; it < 8; ++it) {
                int d = (it*4 + d4) * 4;
                float4 f = *(const float4*)(kp + d);
                Kt[(d+0)*64 + m] = f.x;
                Kt[(d+1)*64 + m] = f.y;
                Kt[(d+2)*64 + m] = f.z;
                Kt[(d+3)*64 + m] = f.w;
            }
            #pragma unroll
            for (int it = 0; it < 8; ++it) {
                int fi = tid + 256*it;
                int r  = fi >> 5;
                int c4 = (fi & 31) << 2;
                *(float4*)&Vs[r*128 + c4] =
                    *(const float4*)(V + (size_t)(b*T_ + jt*64 + r) * NKV_ + kvh*128 + c4);
            }
        }
        __syncthreads();

        float s[4][4];
        #pragma unroll
        for (int i = 0; i < 4; ++i)
            #pragma unroll
            for (int j = 0; j < 4; ++j) s[i][j] = 0.f;
        #pragma unroll 4
        for (int d = 0; d < 128; ++d) {
            float qa[4], kb[4];
            *(float4*)qa = *(const float4*)&Qt[d*64 + ty*4];
            *(float4*)kb = *(const float4*)&Kt[d*64 + tx*4];
            #pragma unroll
            for (int i = 0; i < 4; ++i)
                #pragma unroll
                for (int j = 0; j < 4; ++j)
                    s[i][j] = fmaf(qa[i], kb[j], s[i][j]);
        }

        if (jt == qt) {
            #pragma unroll
            for (int i = 0; i < 4; ++i)
                #pragma unroll
                for (int j = 0; j < 4; ++j)
                    if (tx*4 + j > ty*4 + i) s[i][j] = -1e30f;
        }

        #pragma unroll
        for (int i = 0; i < 4; ++i) {
            float rm = fmaxf(fmaxf(s[i][0], s[i][1]), fmaxf(s[i][2], s[i][3]));
            rm = fmaxf(rm, __shfl_xor_sync(0xffffffffu, rm, 8));
            rm = fmaxf(rm, __shfl_xor_sync(0xffffffffu, rm, 4));
            rm = fmaxf(rm, __shfl_xor_sync(0xffffffffu, rm, 2));
            rm = fmaxf(rm, __shfl_xor_sync(0xffffffffu, rm, 1));
            float mn   = fmaxf(mi[i], rm);
            float corr = __expf(mi[i] - mn);
            mi[i] = mn;
            float rs = 0.f;
            #pragma unroll
            for (int j = 0; j < 4; ++j) { s[i][j] = __expf(s[i][j] - mn); rs += s[i][j]; }
            rs += __shfl_xor_sync(0xffffffffu, rs, 8);
            rs += __shfl_xor_sync(0xffffffffu, rs, 4);
            rs += __shfl_xor_sync(0xffffffffu, rs, 2);
            rs += __shfl_xor_sync(0xffffffffu, rs, 1);
            li[i] = li[i]*corr + rs;
            *(float4*)&Ps[(ty*4 + i)*64 + tx*4] = make_float4(s[i][0], s[i][1], s[i][2], s[i][3]);
            #pragma unroll
            for (int c = 0; c < 8; ++c) O[i][c] *= corr;
        }
        __syncthreads();

        #pragma unroll 2
        for (int n = 0; n < 64; ++n) {
            float p0 = Ps[(ty*4+0)*64 + n];
            float p1 = Ps[(ty*4+1)*64 + n];
            float p2 = Ps[(ty*4+2)*64 + n];
            float p3 = Ps[(ty*4+3)*64 + n];
            float vb[8];
            *(float4*)vb     = *(const float4*)&Vs[n*128 + tx*8];
            *(float4*)(vb+4) = *(const float4*)&Vs[n*128 + tx*8 + 4];
            #pragma unroll
            for (int c = 0; c < 8; ++c) {
                O[0][c] = fmaf(p0, vb[c], O[0][c]);
                O[1][c] = fmaf(p1, vb[c], O[1][c]);
                O[2][c] = fmaf(p2, vb[c], O[2][c]);
                O[3][c] = fmaf(p3, vb[c], O[3][c]);
            }
        }
    }

    #pragma unroll
    for (int i = 0; i < 4; ++i) {
        float inv = 1.0f / li[i];
        float* op = Out + (size_t)(b*T_ + qt*64 + ty*4 + i) * NQ_ + h*128 + tx*8;
        *(float4*)op     = make_float4(rna_tf32(O[i][0]*inv), rna_tf32(O[i][1]*inv),
                                       rna_tf32(O[i][2]*inv), rna_tf32(O[i][3]*inv));
        *(float4*)(op+4) = make_float4(rna_tf32(O[i][4]*inv), rna_tf32(O[i][5]*inv),
                                       rna_tf32(O[i][6]*inv), rna_tf32(O[i][7]*inv));
    }
}

// ---------------------------------------------------------------------------
__global__ void zero_tail_kernel(float* __restrict__ out, long start, long total) {
    long idx = start + blockIdx.x * (long)blockDim.x + threadIdx.x;
    if (idx < total) out[idx] = 0.f;
}

// ---------------------------------------------------------------------------
extern "C" void kernel_launch(void* const* d_in, const int* in_sizes, int n_in,
                              void* d_out, int out_size) {
    const float* x  = (const float*)d_in[0];
    const float* Wq = (const float*)d_in[1];
    const float* Wk = (const float*)d_in[2];
    const float* Wv = (const float*)d_in[3];
    const float* Wo = (const float*)d_in[4];
    float* out = (float*)d_out;

    float *q, *k, *v, *att, *xr, *wq, *wk, *wv, *wo, *rope;
    cudaGetSymbolAddress((void**)&q,    g_q);
    cudaGetSymbolAddress((void**)&k,    g_k);
    cudaGetSymbolAddress((void**)&v,    g_v);
    cudaGetSymbolAddress((void**)&att,  g_att);
    cudaGetSymbolAddress((void**)&xr,   g_xr);
    cudaGetSymbolAddress((void**)&wq,   g_wq);
    cudaGetSymbolAddress((void**)&wk,   g_wk);
    cudaGetSymbolAddress((void**)&wv,   g_wv);
    cudaGetSymbolAddress((void**)&wo,   g_wo);
    cudaGetSymbolAddress((void**)&rope, g_rope);

    rope_table_kernel<<<(T_*64 + 255)/256, 256>>>(rope);

    // RNA-round operands to tf32 (removes correlated truncation bias)
    round_tf32_kernel<<<(M_*(long)DM_/4 + 255)/256, 256>>>(x,  xr, M_*(long)DM_/4);
    round_tf32_kernel<<<(NQ_*(long)DM_/4 + 255)/256, 256>>>(Wq, wq, NQ_*(long)DM_/4);
    round_tf32_kernel<<<(NKV_*(long)DM_/4+ 255)/256, 256>>>(Wk, wk, NKV_*(long)DM_/4);
    round_tf32_kernel<<<(NKV_*(long)DM_/4+ 255)/256, 256>>>(Wv, wv, NKV_*(long)DM_/4);
    round_tf32_kernel<<<(DM_*(long)NQ_/4 + 255)/256, 256>>>(Wo, wo, DM_*(long)NQ_/4);

    const int gsm = 2 * STAGE_B;   // 81920 (also covers 66 KB C-stage)
    cudaFuncSetAttribute(tc_gemm<true >, cudaFuncAttributeMaxDynamicSharedMemorySize, gsm);
    cudaFuncSetAttribute(tc_gemm<false>, cudaFuncAttributeMaxDynamicSharedMemorySize, gsm);

    dim3 blk(256);
    tc_gemm<true ><<<dim3(NQ_ /128, M_/128), blk, gsm>>>(xr, wq, q, M_, NQ_,  DM_, rope);
    tc_gemm<true ><<<dim3(NKV_/128, M_/128), blk, gsm>>>(xr, wk, k, M_, NKV_, DM_, rope);
    tc_gemm<false><<<dim3(NKV_/128, M_/128), blk, gsm>>>(xr, wv, v, M_, NKV_, DM_, nullptr);

    const int fsm = (128*64 + 128*64 + 64*128 + 64*64) * (int)sizeof(float);  // 114688
    cudaFuncSetAttribute(flash_kernel, cudaFuncAttributeMaxDynamicSharedMemorySize, fsm);
    flash_kernel<<<dim3(T_/64, H_, B_), dim3(256), fsm>>>(q, k, v, att);

    tc_gemm<false><<<dim3(NQ_/128, M_/128), blk, gsm>>>(att, wo, out, M_, NQ_, DM_, nullptr);

    long main_elems = (long)M_ * NQ_;
    long tail = (long)out_size - main_elems;
    if (tail > 0) {
        int nb = (int)((tail + 255) / 256);
        zero_tail_kernel<<<nb, 256>>>(out, main_elems, (long)out_size);
    }
}

// round 4
// speedup vs baseline: 3.7402x; 2.1118x over previous
#include <cuda_runtime.h>
#include <math.h>
#include <stdint.h>

// Problem constants
#define B_    4
#define T_    2048
#define DM_   2048
#define H_    16
#define HKV_  4
#define D_    128
#define M_    (B_*T_)      // 8192 tokens
#define NQ_   (H_*D_)      // 2048
#define NKV_  (HKV_*D_)    // 512

// Scratch (device globals: allocation-free per harness rules)
__device__ float g_q  [M_*NQ_];
__device__ float g_k  [M_*NKV_];
__device__ float g_v  [M_*NKV_];
__device__ float g_att[M_*NQ_];
__device__ float g_xr [M_*DM_];
__device__ float g_wq [NQ_*DM_];
__device__ float g_wk [NKV_*DM_];
__device__ float g_wv [NKV_*DM_];
__device__ float g_wo [DM_*NQ_];
__device__ float g_rope[T_*64*2];

// ---------------------------------------------------------------------------
// Helpers
// ---------------------------------------------------------------------------
__device__ __forceinline__ uint32_t smem_u32(const void* p) {
    uint32_t a;
    asm("{ .reg .u64 t; cvta.to.shared.u64 t, %1; cvt.u32.u64 %0, t; }" : "=r"(a) : "l"(p));
    return a;
}
__device__ __forceinline__ float rna_tf32(float v) {
    uint32_t b;
    asm("cvt.rna.tf32.f32 %0, %1;" : "=r"(b) : "f"(v));
    return __uint_as_float(b);
}
__device__ __forceinline__ uint32_t rna_tf32_u(float v) {
    uint32_t b;
    asm("cvt.rna.tf32.f32 %0, %1;" : "=r"(b) : "f"(v));
    return b;
}

#define CP_ASYNC16(dst, src) \
    asm volatile("cp.async.cg.shared.global [%0], [%1], 16;" :: "r"(dst), "l"(src) : "memory")
#define CP_COMMIT()  asm volatile("cp.async.commit_group;" ::: "memory")
#define CP_WAIT(n)   asm volatile("cp.async.wait_group %0;" :: "n"(n) : "memory")

// mma.sync m16n8k8 tf32 (family-portable)
#define MMA_TF32(c, a, b) \
    asm volatile("mma.sync.aligned.m16n8k8.row.col.f32.tf32.tf32.f32 " \
        "{%0,%1,%2,%3}, {%4,%5,%6,%7}, {%8,%9}, {%0,%1,%2,%3};" \
        : "+f"((c)[0]), "+f"((c)[1]), "+f"((c)[2]), "+f"((c)[3]) \
        : "r"((a)[0]), "r"((a)[1]), "r"((a)[2]), "r"((a)[3]), \
          "r"((b)[0]), "r"((b)[1]))

// ---------------------------------------------------------------------------
__global__ void round_tf32_kernel(const float* __restrict__ in, float* __restrict__ out, long n4) {
    long i = (blockIdx.x * (long)blockDim.x + threadIdx.x);
    if (i >= n4) return;
    float4 v = ((const float4*)in)[i];
    v.x = rna_tf32(v.x); v.y = rna_tf32(v.y); v.z = rna_tf32(v.z); v.w = rna_tf32(v.w);
    ((float4*)out)[i] = v;
}

__global__ void rope_table_kernel(float* __restrict__ tab) {
    int idx = blockIdx.x * blockDim.x + threadIdx.x;
    if (idx >= T_ * 64) return;
    int t = idx >> 6, f = idx & 63;
    double invf = exp(-((double)f / 64.0) * log(10000.0));
    float ang = (float)t * (float)invf;
    tab[idx*2 + 0] = (float)cos((double)ang);
    tab[idx*2 + 1] = (float)sin((double)ang);
}

// ---------------------------------------------------------------------------
// HMMA tf32 GEMM: C[M,N] = A[M,K] @ W[N,K]^T (round 3, passing; + ROUND param)
// ---------------------------------------------------------------------------
#define STAGE_F 10240
#define STAGE_B (STAGE_F*4)

template<bool FUSE, bool ROUND>
__global__ __launch_bounds__(256)
void tc_gemm(const float* __restrict__ A, const float* __restrict__ W,
             float* __restrict__ C, int M, int N, int K,
             const float* __restrict__ rope)
{
    extern __shared__ float smf[];
    const uint32_t sbase = smem_u32(smf);

    const int tid  = threadIdx.x;
    const int lane = tid & 31;
    const int wid  = tid >> 5;
    const int warp_m = wid >> 2;
    const int warp_n = wid & 3;
    const int bx = blockIdx.x, by = blockIdx.y;

    const float* Ab = A + (size_t)(by * 128) * K;
    const float* Wb = W + (size_t)(bx * 128) * K;

    float acc[4][4][4];
    #pragma unroll
    for (int mi = 0; mi < 4; ++mi)
        #pragma unroll
        for (int ni = 0; ni < 4; ++ni)
            #pragma unroll
            for (int e = 0; e < 4; ++e) acc[mi][ni][e] = 0.f;

    const int KT = K >> 5;

    auto load_stage = [&](int s, int kt) {
        uint32_t aS = sbase + s * STAGE_B;
        uint32_t bS = aS + 20480;
        const float* ap = Ab + kt * 32;
        const float* wp = Wb + kt * 32;
        #pragma unroll
        for (int it = 0; it < 4; ++it) {
            int idx = it * 256 + tid;
            int row = idx >> 3, seg = idx & 7;
            uint32_t so = (uint32_t)row * 160 + (uint32_t)seg * 16;
            CP_ASYNC16(aS + so, ap + (size_t)row * K + seg * 4);
            CP_ASYNC16(bS + so, wp + (size_t)row * K + seg * 4);
        }
    };

    load_stage(0, 0);
    CP_COMMIT();

    for (int kt = 0; kt < KT; ++kt) {
        const int cur = kt & 1;
        if (kt + 1 < KT) {
            load_stage(cur ^ 1, kt + 1);
            CP_COMMIT();
            CP_WAIT(1);
        } else {
            CP_WAIT(0);
        }
        __syncthreads();

        const float* As_ = smf + cur * STAGE_F + warp_m * (64 * 40);
        const float* Bs_ = smf + cur * STAGE_F + 5120 + warp_n * (32 * 40);

        #pragma unroll
        for (int ks = 0; ks < 4; ++ks) {
            const int col = ks * 8 + 2 * (lane & 3);
            uint32_t a[4][4], b[4][2];
            #pragma unroll
            for (int ni = 0; ni < 4; ++ni) {
                float2 t = *(const float2*)&Bs_[(ni * 8 + (lane >> 2)) * 40 + col];
                b[ni][0] = __float_as_uint(t.x);
                b[ni][1] = __float_as_uint(t.y);
            }
            #pragma unroll
            for (int mi = 0; mi < 4; ++mi) {
                const int r = mi * 16 + (lane >> 2);
                float2 t0 = *(const float2*)&As_[r * 40 + col];
                float2 t1 = *(const float2*)&As_[(r + 8) * 40 + col];
                a[mi][0] = __float_as_uint(t0.x);
                a[mi][2] = __float_as_uint(t0.y);
                a[mi][1] = __float_as_uint(t1.x);
                a[mi][3] = __float_as_uint(t1.y);
            }
            #pragma unroll
            for (int mi = 0; mi < 4; ++mi)
                #pragma unroll
                for (int ni = 0; ni < 4; ++ni)
                    MMA_TF32(acc[mi][ni], a[mi], b[ni]);
        }
        __syncthreads();
    }

    if (!FUSE) {
        #pragma unroll
        for (int mi = 0; mi < 4; ++mi) {
            const int r = by * 128 + warp_m * 64 + mi * 16 + (lane >> 2);
            #pragma unroll
            for (int ni = 0; ni < 4; ++ni) {
                const int c = bx * 128 + warp_n * 32 + ni * 8 + (lane & 3) * 2;
                float e0 = acc[mi][ni][0], e1 = acc[mi][ni][1];
                float e2 = acc[mi][ni][2], e3 = acc[mi][ni][3];
                if (ROUND) { e0 = rna_tf32(e0); e1 = rna_tf32(e1); e2 = rna_tf32(e2); e3 = rna_tf32(e3); }
                *(float2*)&C[(size_t)r * N + c]       = make_float2(e0, e1);
                *(float2*)&C[(size_t)(r + 8) * N + c] = make_float2(e2, e3);
            }
        }
    } else {
        float* Cs = smf;
        #pragma unroll
        for (int mi = 0; mi < 4; ++mi) {
            const int r = warp_m * 64 + mi * 16 + (lane >> 2);
            #pragma unroll
            for (int ni = 0; ni < 4; ++ni) {
                const int c = warp_n * 32 + ni * 8 + (lane & 3) * 2;
                Cs[r * 129 + c]           = acc[mi][ni][0];
                Cs[r * 129 + c + 1]       = acc[mi][ni][1];
                Cs[(r + 8) * 129 + c]     = acc[mi][ni][2];
                Cs[(r + 8) * 129 + c + 1] = acc[mi][ni][3];
            }
        }
        __syncthreads();
        if (tid < 128) {
            const int row = by * 128 + tid;
            const float* cr = Cs + tid * 129;
            float ss = 0.f;
            #pragma unroll 16
            for (int j = 0; j < 128; ++j) ss += cr[j] * cr[j];
            const float sc = rsqrtf(ss * (1.0f/128.0f) + 1.1920928955078125e-07f);
            const float* rp = rope + (row & (T_ - 1)) * 128;
            float* op = C + (size_t)row * N + bx * 128;
            #pragma unroll
            for (int f4 = 0; f4 < 64; f4 += 4) {
                float4 o1, o2;
                #pragma unroll
                for (int e = 0; e < 4; ++e) {
                    const int f = f4 + e;
                    const float v1 = cr[f] * sc;
                    const float v2 = cr[f + 64] * sc;
                    const float cz = rp[2*f], sz = rp[2*f + 1];
                    float r1 =  v1 * cz + v2 * sz;
                    float r2 = -v1 * sz + v2 * cz;
                    if (ROUND) { r1 = rna_tf32(r1); r2 = rna_tf32(r2); }
                    (&o1.x)[e] = r1;
                    (&o2.x)[e] = r2;
                }
                *(float4*)(op + f4)      = o1;
                *(float4*)(op + f4 + 64) = o2;
            }
        }
    }
}

// ---------------------------------------------------------------------------
// Tensor-core flash attention (tf32 mma.sync), causal, GQA.
// BM=128 (8 warps x m16), BN=64, D=128. Q fragments persistent in registers.
// K/V double-buffered cp.async (prefetch distance 2). P via smem round-trip.
// Strides: K/V/Qstage 136 floats (conflict-free float2 frag loads),
//          P 68 floats (conflict-free A-frag loads).
// Smem: P[128x68] | K0 | K1 | V0 | V1 (each 64x136) = 174080 B.
// Q is staged through the K0+K1 region before the pipeline starts.
// ---------------------------------------------------------------------------
#define FKV 8704   // floats per K/V buffer (64*136)

__global__ __launch_bounds__(256, 1)
void flash_tc(const float* __restrict__ Q, const float* __restrict__ K,
              const float* __restrict__ V, float* __restrict__ Out)
{
    extern __shared__ float sm[];
    float* Psm = sm;                       // 128 x 68
    float* Ks0 = sm + FKV;                 // 64 x 136
    float* Ks1 = sm + 2*FKV;
    float* Vs0 = sm + 3*FKV;
    float* Vs1 = sm + 4*FKV;
    const uint32_t sb = smem_u32(sm);

    const int qt  = (int)gridDim.x - 1 - (int)blockIdx.x;   // big tiles first
    const int h   = blockIdx.y;
    const int b   = blockIdx.z;
    const int kvh = h >> 2;
    const int tid = threadIdx.x;
    const int lane = tid & 31;
    const int wm   = tid >> 5;         // warp id = m-block
    const int g    = lane >> 2;        // group id (row within m16)
    const int q4   = lane & 3;         // thread-in-group

    const float scale = 0.08838834764831843f;   // 1/sqrt(128)

    // ---- stage Q tile (128 x 128) into K0+K1 region, stride 136 ----
    {
        const float* qp = Q + (size_t)(b*T_ + qt*128) * NQ_ + h*128;
        uint32_t qdst = sb + FKV*4;   // byte addr of Ks0
        #pragma unroll
        for (int it = 0; it < 16; ++it) {
            int idx = it * 256 + tid;
            int row = idx >> 5, seg = idx & 31;
            CP_ASYNC16(qdst + ((uint32_t)row*136 + seg*4)*4, qp + (size_t)row*NQ_ + seg*4);
        }
        CP_COMMIT();
        CP_WAIT(0);
        __syncthreads();
    }

    // ---- extract Q fragments (scaled, tf32-rounded) ----
    uint32_t qf[16][4];
    {
        const float* qs = Ks0 + (wm*16 + g)*136 + 2*q4;
        #pragma unroll
        for (int ks = 0; ks < 16; ++ks) {
            float2 t0 = *(const float2*)(qs + ks*8);
            float2 t1 = *(const float2*)(qs + ks*8 + 8*136);
            qf[ks][0] = rna_tf32_u(t0.x * scale);
            qf[ks][2] = rna_tf32_u(t0.y * scale);
            qf[ks][1] = rna_tf32_u(t1.x * scale);
            qf[ks][3] = rna_tf32_u(t1.y * scale);
        }
    }
    __syncthreads();   // Q region free -> K buffers

    const int njt = 2*qt + 2;

    // ---- K/V tile loaders ----
    auto load_k = [&](int jt) {
        float* Kd = (jt & 1) ? Ks1 : Ks0;
        uint32_t kd = sb + (uint32_t)((jt & 1) ? 2*FKV : FKV) * 4;
        const float* kp = K + (size_t)(b*T_ + jt*64) * NKV_ + kvh*128;
        (void)Kd;
        #pragma unroll
        for (int it = 0; it < 8; ++it) {
            int idx = it * 256 + tid;
            int row = idx >> 5, seg = idx & 31;
            CP_ASYNC16(kd + ((uint32_t)row*136 + seg*4)*4, kp + (size_t)row*NKV_ + seg*4);
        }
    };
    auto load_v = [&](int jt) {
        uint32_t vd = sb + (uint32_t)((jt & 1) ? 4*FKV : 3*FKV) * 4;
        const float* vp = V + (size_t)(b*T_ + jt*64) * NKV_ + kvh*128;
        #pragma unroll
        for (int it = 0; it < 8; ++it) {
            int idx = it * 256 + tid;
            int row = idx >> 5, seg = idx & 31;
            CP_ASYNC16(vd + ((uint32_t)row*136 + seg*4)*4, vp + (size_t)row*NKV_ + seg*4);
        }
    };

    // prologue: groups G0={K0,V0}, G1={K1,V1}
    load_k(0); load_v(0); CP_COMMIT();
    load_k(1); load_v(1); CP_COMMIT();

    float m0 = -1e30f, m1 = -1e30f, l0 = 0.f, l1 = 0.f;
    float O[16][4];
    #pragma unroll
    for (int nf = 0; nf < 16; ++nf)
        #pragma unroll
        for (int e = 0; e < 4; ++e) O[nf][e] = 0.f;

    const int row_g0 = qt*128 + wm*16 + g;      // global row of elems 0,1
    float* Prow = Psm + (wm*16 + g)*68;

    for (int jt = 0; jt < njt; ++jt) {
        const int cur = jt & 1;
        if (jt == 0) { CP_WAIT(1); } else { CP_WAIT(2); }
        __syncthreads();   // K[cur],V[cur] ready; prev-iter P readers done

        const float* Kc = cur ? Ks1 : Ks0;
        const float* Vc = cur ? Vs1 : Vs0;

        // ---- S = Q @ K^T ----
        float S[8][4];
        #pragma unroll
        for (int nf = 0; nf < 8; ++nf)
            #pragma unroll
            for (int e = 0; e < 4; ++e) S[nf][e] = 0.f;

        #pragma unroll
        for (int ks = 0; ks < 16; ++ks) {
            const float* kb = Kc + g*136 + ks*8 + 2*q4;
            #pragma unroll
            for (int nf = 0; nf < 8; ++nf) {
                float2 t = *(const float2*)(kb + nf*8*136);
                uint32_t bb[2] = { __float_as_uint(t.x), __float_as_uint(t.y) };
                MMA_TF32(S[nf], qf[ks], bb);
            }
        }

        // ---- causal mask (only the 2 diagonal-straddling tiles) ----
        if (jt >= 2*qt) {
            const int colb = jt*64 + 2*q4;
            #pragma unroll
            for (int nf = 0; nf < 8; ++nf) {
                const int c0 = colb + nf*8;
                if (c0     > row_g0)     S[nf][0] = -1e30f;
                if (c0 + 1 > row_g0)     S[nf][1] = -1e30f;
                if (c0     > row_g0 + 8) S[nf][2] = -1e30f;
                if (c0 + 1 > row_g0 + 8) S[nf][3] = -1e30f;
            }
        }

        // ---- online softmax ----
        float rm0 = -1e30f, rm1 = -1e30f;
        #pragma unroll
        for (int nf = 0; nf < 8; ++nf) {
            rm0 = fmaxf(rm0, fmaxf(S[nf][0], S[nf][1]));
            rm1 = fmaxf(rm1, fmaxf(S[nf][2], S[nf][3]));
        }
        rm0 = fmaxf(rm0, __shfl_xor_sync(0xffffffffu, rm0, 1));
        rm0 = fmaxf(rm0, __shfl_xor_sync(0xffffffffu, rm0, 2));
        rm1 = fmaxf(rm1, __shfl_xor_sync(0xffffffffu, rm1, 1));
        rm1 = fmaxf(rm1, __shfl_xor_sync(0xffffffffu, rm1, 2));

        const float mn0 = fmaxf(m0, rm0), mn1 = fmaxf(m1, rm1);
        const float corr0 = __expf(m0 - mn0), corr1 = __expf(m1 - mn1);
        m0 = mn0; m1 = mn1;

        float rs0 = 0.f, rs1 = 0.f;
        #pragma unroll
        for (int nf = 0; nf < 8; ++nf) {
            S[nf][0] = __expf(S[nf][0] - mn0);
            S[nf][1] = __expf(S[nf][1] - mn0);
            S[nf][2] = __expf(S[nf][2] - mn1);
            S[nf][3] = __expf(S[nf][3] - mn1);
            rs0 += S[nf][0] + S[nf][1];
            rs1 += S[nf][2] + S[nf][3];
        }
        rs0 += __shfl_xor_sync(0xffffffffu, rs0, 1);
        rs0 += __shfl_xor_sync(0xffffffffu, rs0, 2);
        rs1 += __shfl_xor_sync(0xffffffffu, rs1, 1);
        rs1 += __shfl_xor_sync(0xffffffffu, rs1, 2);
        l0 = l0*corr0 + rs0;
        l1 = l1*corr1 + rs1;

        #pragma unroll
        for (int nf = 0; nf < 16; ++nf) {
            O[nf][0] *= corr0; O[nf][1] *= corr0;
            O[nf][2] *= corr1; O[nf][3] *= corr1;
        }

        // ---- write P (tf32-rounded) to smem ----
        #pragma unroll
        for (int nf = 0; nf < 8; ++nf) {
            const int c = nf*8 + 2*q4;
            *(float2*)(Prow + c)        = make_float2(rna_tf32(S[nf][0]), rna_tf32(S[nf][1]));
            *(float2*)(Prow + 8*68 + c) = make_float2(rna_tf32(S[nf][2]), rna_tf32(S[nf][3]));
        }
        __syncthreads();   // P visible; all warps done reading K[cur]

        if (jt + 2 < njt) load_k(jt + 2);
        CP_COMMIT();

        // ---- O += P @ V ----
        #pragma unroll
        for (int ks = 0; ks < 8; ++ks) {
            uint32_t a[4];
            a[0] = __float_as_uint(Prow[ks*8 + q4]);
            a[2] = __float_as_uint(Prow[ks*8 + q4 + 4]);
            a[1] = __float_as_uint(Prow[8*68 + ks*8 + q4]);
            a[3] = __float_as_uint(Prow[8*68 + ks*8 + q4 + 4]);
            const float* vb = Vc + (ks*8 + q4)*136 + g;
            #pragma unroll
            for (int nf = 0; nf < 16; ++nf) {
                uint32_t bb[2] = { __float_as_uint(vb[nf*8]),
                                   __float_as_uint(vb[nf*8 + 4*136]) };
                MMA_TF32(O[nf], a, bb);
            }
        }
        __syncthreads();   // all warps done reading V[cur]

        if (jt + 2 < njt) load_v(jt + 2);
        CP_COMMIT();
    }

    // ---- epilogue: normalize, round to tf32, store ----
    const float inv0 = 1.0f / l0;
    const float inv1 = 1.0f / l1;
    float* o0 = Out + (size_t)(b*T_ + row_g0)     * NQ_ + h*128 + 2*q4;
    float* o1 = Out + (size_t)(b*T_ + row_g0 + 8) * NQ_ + h*128 + 2*q4;
    #pragma unroll
    for (int nf = 0; nf < 16; ++nf) {
        *(float2*)(o0 + nf*8) = make_float2(rna_tf32(O[nf][0]*inv0), rna_tf32(O[nf][1]*inv0));
        *(float2*)(o1 + nf*8) = make_float2(rna_tf32(O[nf][2]*inv1), rna_tf32(O[nf][3]*inv1));
    }
}

// ---------------------------------------------------------------------------
__global__ void zero_tail_kernel(float* __restrict__ out, long start, long total) {
    long idx = start + blockIdx.x * (long)blockDim.x + threadIdx.x;
    if (idx < total) out[idx] = 0.f;
}

// ---------------------------------------------------------------------------
extern "C" void kernel_launch(void* const* d_in, const int* in_sizes, int n_in,
                              void* d_out, int out_size) {
    const float* x  = (const float*)d_in[0];
    const float* Wq = (const float*)d_in[1];
    const float* Wk = (const float*)d_in[2];
    const float* Wv = (const float*)d_in[3];
    const float* Wo = (const float*)d_in[4];
    float* out = (float*)d_out;

    float *q, *k, *v, *att, *xr, *wq, *wk, *wv, *wo, *rope;
    cudaGetSymbolAddress((void**)&q,    g_q);
    cudaGetSymbolAddress((void**)&k,    g_k);
    cudaGetSymbolAddress((void**)&v,    g_v);
    cudaGetSymbolAddress((void**)&att,  g_att);
    cudaGetSymbolAddress((void**)&xr,   g_xr);
    cudaGetSymbolAddress((void**)&wq,   g_wq);
    cudaGetSymbolAddress((void**)&wk,   g_wk);
    cudaGetSymbolAddress((void**)&wv,   g_wv);
    cudaGetSymbolAddress((void**)&wo,   g_wo);
    cudaGetSymbolAddress((void**)&rope, g_rope);

    rope_table_kernel<<<(T_*64 + 255)/256, 256>>>(rope);

    round_tf32_kernel<<<(M_*(long)DM_/4 + 255)/256, 256>>>(x,  xr, M_*(long)DM_/4);
    round_tf32_kernel<<<(NQ_*(long)DM_/4 + 255)/256, 256>>>(Wq, wq, NQ_*(long)DM_/4);
    round_tf32_kernel<<<(NKV_*(long)DM_/4+ 255)/256, 256>>>(Wk, wk, NKV_*(long)DM_/4);
    round_tf32_kernel<<<(NKV_*(long)DM_/4+ 255)/256, 256>>>(Wv, wv, NKV_*(long)DM_/4);
    round_tf32_kernel<<<(DM_*(long)NQ_/4 + 255)/256, 256>>>(Wo, wo, DM_*(long)NQ_/4);

    const int gsm = 2 * STAGE_B;
    cudaFuncSetAttribute((tc_gemm<true , false>), cudaFuncAttributeMaxDynamicSharedMemorySize, gsm);
    cudaFuncSetAttribute((tc_gemm<true , true >), cudaFuncAttributeMaxDynamicSharedMemorySize, gsm);
    cudaFuncSetAttribute((tc_gemm<false, true >), cudaFuncAttributeMaxDynamicSharedMemorySize, gsm);
    cudaFuncSetAttribute((tc_gemm<false, false>), cudaFuncAttributeMaxDynamicSharedMemorySize, gsm);

    dim3 blk(256);
    // q: keep fp32 (flash scales+rounds it); k,v: round to tf32 at write
    tc_gemm<true , false><<<dim3(NQ_ /128, M_/128), blk, gsm>>>(xr, wq, q, M_, NQ_,  DM_, rope);
    tc_gemm<true , true ><<<dim3(NKV_/128, M_/128), blk, gsm>>>(xr, wk, k, M_, NKV_, DM_, rope);
    tc_gemm<false, true ><<<dim3(NKV_/128, M_/128), blk, gsm>>>(xr, wv, v, M_, NKV_, DM_, nullptr);

    const int fsm = 5 * FKV * 4;   // 174080 B
    cudaFuncSetAttribute(flash_tc, cudaFuncAttributeMaxDynamicSharedMemorySize, fsm);
    flash_tc<<<dim3(T_/128, H_, B_), dim3(256), fsm>>>(q, k, v, att);

    tc_gemm<false, false><<<dim3(NQ_/128, M_/128), blk, gsm>>>(att, wo, out, M_, NQ_, DM_, nullptr);

    long main_elems = (long)M_ * NQ_;
    long tail = (long)out_size - main_elems;
    if (tail > 0) {
        int nb = (int)((tail + 255) / 256);
        zero_tail_kernel<<<nb, 256>>>(out, main_elems, (long)out_size);
    }
}